// round 12
// baseline (speedup 1.0000x reference)
#include <cuda_runtime.h>

#define TT 128
#define BB 512
#define QQ 50
#define BQ (BB * QQ)                 // 25600
#define NUNITS ((TT - 1) * BB)       // 65024
#define GAMMA_F 0.99f
#define UNITS 10                     // units per k_pairs block (10*25 = 250 thr)
#define RST 52                       // smem row stride, 16B aligned

// Discounted returns, row gu = t*BB+b at [gu*QQ .. gu*QQ+49].
__device__ float g_ret[(TT - 1) * BQ];

// ---------------------------------------------------------------------------
// Kernel 1: backward recurrence, one block per b, intra-block 4-way
// segmented scan. Threads (c,q): c = 32-t chunk, q = quantile chain.
//   Phase A: per-chunk affine composite (parallel, 8 warps active)
//   Phase B: compose seeds (<=3 fmas)
//   Phase C: 32-step walk + coalesced g_ret stores
// ---------------------------------------------------------------------------
__global__ __launch_bounds__(256)
void k_ret(const float* __restrict__ reward,
           const int*   __restrict__ step_type,
           const float* __restrict__ discount,
           const float* __restrict__ tvalue,
           float*       __restrict__ out)
{
    __shared__ __align__(16) float s_tv[TT][RST];
    __shared__ float s_a[TT], s_r[TT];
    __shared__ int   s_il[TT];
    __shared__ float s_A[4][RST], s_B[4][RST];

    const int tid = threadIdx.x;
    const int b   = blockIdx.x;
    const int c   = tid >> 6;                        // chunk 0..3
    const int q   = tid & 63;                        // chain 0..49 active

    // Stage 128 rows of tvalue[:, b, :] (float2, rows gmem-contiguous 200B)
    for (int idx = tid; idx < TT * (QQ / 2); idx += 256) {
        const int t  = idx / (QQ / 2);
        const int q2 = idx - t * (QQ / 2);
        ((float2*)&s_tv[t][0])[q2] =
            *(const float2*)&tvalue[t * BQ + b * QQ + 2 * q2];
    }
    // Per-t scalars for t = 0..126
    if (tid < TT - 1) {
        const int il = step_type[tid * BB + b];
        s_il[tid] = il;
        s_r[tid]  = reward[(tid + 1) * BB + b];
        s_a[tid]  = (il == 2) ? 0.0f
                              : discount[(tid + 1) * BB + b] * GAMMA_F;
    }
    if (tid == 0) out[(TT - 1) * BB + b] = 0.0f;     // poisoned last row
    __syncthreads();

    const int lo = 32 * c;
    const int hi = (c == 3) ? (TT - 2) : (lo + 31);  // 126 for c=3

    // ---- Phase A: 32-step (31 for c=3) affine composite ----
    if (q < QQ) {
        float A = 1.0f, Bv = 0.0f;
        #pragma unroll 4
        for (int t = hi; t >= lo; --t) {
            float tv = s_tv[t][q];
            float a  = s_a[t];
            float bb = (s_il[t] == 2) ? tv : s_r[t];
            A  = a * A;
            Bv = fmaf(a, Bv, bb);
        }
        s_A[c][q] = A;
        s_B[c][q] = Bv;
    }
    __syncthreads();

    // ---- Phase B + C: seed compose, then walk + store ----
    if (q < QQ) {
        float carry = s_tv[TT - 1][q];               // rets[127]
        #pragma unroll
        for (int cc = 3; cc >= 1; --cc)
            if (cc > c) carry = fmaf(s_A[cc][q], carry, s_B[cc][q]);
        // carry == rets[hi+1]

        #pragma unroll 4
        for (int t = hi; t >= lo; --t) {
            float tv = s_tv[t][q];
            float a  = s_a[t];
            float bb = (s_il[t] == 2) ? tv : s_r[t];
            carry = fmaf(a, carry, bb);
            g_ret[t * BQ + b * QQ + q] = carry;
        }
    }
}

// ---------------------------------------------------------------------------
// Kernel 2: pairwise quantile-Huber (R11 form — measured 38.0 us, at the
// rt=3 register-bank structural mix; left untouched).
//   x = ret_i - v_j;  m = min(|x|,1);  c = (x&sign)|m;  t = x - 0.5c
//   h = c*t, sgn(x)*h = m*t ;  loss_j = 0.5*S + (tau_j-0.5)*D
// ---------------------------------------------------------------------------

#define PAIR2(r2_, nv2_, S2_, D2_) do {                                        \
    unsigned long long x2_, c2_, m2_, t2_;                                     \
    asm("add.rn.f32x2 %0, %1, %2;" : "=l"(x2_) : "l"(r2_), "l"(nv2_));         \
    float xl_, xh_;                                                            \
    asm("mov.b64 {%0, %1}, %2;" : "=f"(xl_), "=f"(xh_) : "l"(x2_));            \
    float ml_ = fminf(fabsf(xl_), 1.0f);                                       \
    float mh_ = fminf(fabsf(xh_), 1.0f);                                       \
    float cl_ = __int_as_float((__float_as_int(xl_) & 0x80000000) |            \
                               __float_as_int(ml_));                           \
    float ch_ = __int_as_float((__float_as_int(xh_) & 0x80000000) |            \
                               __float_as_int(mh_));                           \
    asm("mov.b64 %0, {%1, %2};" : "=l"(c2_) : "f"(cl_), "f"(ch_));             \
    asm("mov.b64 %0, {%1, %2};" : "=l"(m2_) : "f"(ml_), "f"(mh_));             \
    asm("fma.rn.f32x2 %0, %1, %2, %3;" : "=l"(t2_)                             \
        : "l"(c2_), "l"(MH2), "l"(x2_));                                       \
    asm("fma.rn.f32x2 %0, %1, %2, %0;" : "+l"(S2_) : "l"(c2_), "l"(t2_));      \
    asm("fma.rn.f32x2 %0, %1, %2, %0;" : "+l"(D2_) : "l"(m2_), "l"(t2_));      \
} while (0)

__global__ __launch_bounds__(256)
void k_pairs(const float* __restrict__ value,
             float*       __restrict__ out)
{
    __shared__ __align__(16) float s_ret[UNITS][RST];
    __shared__ float s_part[UNITS][QQ];

    const int tid = threadIdx.x;
    const int gu0 = blockIdx.x * UNITS;
    const int nu  = min(UNITS, NUNITS - gu0);

    const int u  = tid / 25;
    const int jp = tid - u * 25;

    // Stage: 250 float2 loads (rows gu0..gu0+nu-1 are gmem-contiguous).
    if (tid < UNITS * 25 && u < nu)
        ((float2*)&s_ret[u][0])[jp] =
            *(const float2*)&g_ret[gu0 * QQ + 2 * tid];
    __syncthreads();

    if (tid < UNITS * 25 && u < nu) {
        const int gu = gu0 + u;
        const float2 v2 = *(const float2*)&value[gu * QQ + 2 * jp];
        unsigned long long nv2a, nv2b;
        {
            float na = -v2.x, nb = -v2.y;
            asm("mov.b64 %0, {%1, %1};" : "=l"(nv2a) : "f"(na));
            asm("mov.b64 %0, {%1, %1};" : "=l"(nv2b) : "f"(nb));
        }
        const unsigned long long MH2 = 0xBF000000BF000000ULL;   // (-0.5,-0.5)
        unsigned long long S2a = 0, D2a = 0, S2b = 0, D2b = 0;

        const ulonglong2* rp2 = (const ulonglong2*)&s_ret[u][0];
        #pragma unroll
        for (int p = 0; p < 12; ++p) {               // 48 returns via LDS.128
            ulonglong2 rr = rp2[p];
            PAIR2(rr.x, nv2a, S2a, D2a);
            PAIR2(rr.x, nv2b, S2b, D2b);
            PAIR2(rr.y, nv2a, S2a, D2a);
            PAIR2(rr.y, nv2b, S2b, D2b);
        }
        {                                            // returns 48, 49
            unsigned long long rt_ = *(const unsigned long long*)&s_ret[u][48];
            PAIR2(rt_, nv2a, S2a, D2a);
            PAIR2(rt_, nv2b, S2b, D2b);
        }

        float sl, sh, dl, dh;
        asm("mov.b64 {%0, %1}, %2;" : "=f"(sl), "=f"(sh) : "l"(S2a));
        asm("mov.b64 {%0, %1}, %2;" : "=f"(dl), "=f"(dh) : "l"(D2a));
        const float taua = (2 * jp + 0.5f) * (1.0f / QQ);
        s_part[u][2 * jp]     = fmaf(taua - 0.5f, dl + dh, 0.5f * (sl + sh));

        asm("mov.b64 {%0, %1}, %2;" : "=f"(sl), "=f"(sh) : "l"(S2b));
        asm("mov.b64 {%0, %1}, %2;" : "=f"(dl), "=f"(dh) : "l"(D2b));
        const float taub = (2 * jp + 1.5f) * (1.0f / QQ);
        s_part[u][2 * jp + 1] = fmaf(taub - 0.5f, dl + dh, 0.5f * (sl + sh));
    }
    __syncthreads();

    // Deterministic fixed-order j-reduction, one thread per unit.
    if (tid < nu) {
        float s = 0.0f;
        #pragma unroll
        for (int j = 0; j < QQ; ++j) s += s_part[tid][j];
        out[gu0 + tid] = s * (1.0f / QQ);            // out idx t*BB+b == gu
    }
}

extern "C" void kernel_launch(void* const* d_in, const int* in_sizes, int n_in,
                              void* d_out, int out_size)
{
    const float* reward    = (const float*)d_in[0];
    const int*   step_type = (const int*)  d_in[1];
    const float* discount  = (const float*)d_in[2];
    const float* value     = (const float*)d_in[3];
    const float* tvalue    = (const float*)d_in[4];
    float*       out       = (float*)d_out;

    k_ret<<<BB, 256>>>(reward, step_type, discount, tvalue, out);

    const int nblocks = (NUNITS + UNITS - 1) / UNITS;   // 6503
    k_pairs<<<nblocks, 256>>>(value, out);
}